// round 1
// baseline (speedup 1.0000x reference)
#include <cuda_runtime.h>
#include <cuda_bf16.h>

#define S_GRID 7
#define CELLS 49            // 7*7
#define CH 30
#define TILE_ELEMS (CELLS * CH)   // 1470
#define MAXM 16
#define NUMC 20
#define MAXB 16384

// Scratch for deterministic reduction (no device allocation allowed).
__device__ float g_partial[MAXB];

__device__ __forceinline__ float iou_fn(float a0, float a1, float a2, float a3,
                                        float b0, float b1, float b2, float b3) {
    float ax1 = a0 - a2 * 0.5f, ay1 = a1 - a3 * 0.5f;
    float ax2 = a0 + a2 * 0.5f, ay2 = a1 + a3 * 0.5f;
    float bx1 = b0 - b2 * 0.5f, by1 = b1 - b3 * 0.5f;
    float bx2 = b0 + b2 * 0.5f, by2 = b1 + b3 * 0.5f;
    float iw = fmaxf(fminf(ax2, bx2) - fmaxf(ax1, bx1), 0.0f);
    float ih = fmaxf(fminf(ay2, by2) - fmaxf(ay1, by1), 0.0f);
    float inter = iw * ih;
    float uni = a2 * a3 + b2 * b3 - inter;
    return inter / (uni + 1e-6f);
}

__global__ __launch_bounds__(128) void yolo_loss_kernel(
    const float* __restrict__ pred,
    const float* __restrict__ gt_xywh,
    const int*   __restrict__ gt_class) {
    const int b = blockIdx.x;
    const int tid = threadIdx.x;

    __shared__ float tile[TILE_ELEMS];
    __shared__ float4 s_gt[MAXM];
    __shared__ int s_cell[MAXM];
    __shared__ int s_cls[MAXM];
    __shared__ int s_keep[MAXM];
    __shared__ unsigned long long s_obj;
    __shared__ float s_red[4];

    // Coalesced staged load of this image's 1470-float pred slice.
    // Image byte offset = b*5880, 8B-aligned -> float2 is safe.
    const float2* src = reinterpret_cast<const float2*>(pred + (size_t)b * TILE_ELEMS);
    float2* dst = reinterpret_cast<float2*>(tile);
    #pragma unroll
    for (int i = tid; i < TILE_ELEMS / 2; i += 128) dst[i] = src[i];

    if (tid < MAXM) {
        // gt base offset = b*64 floats = 256B aligned -> float4 safe.
        float4 g = reinterpret_cast<const float4*>(gt_xywh + (size_t)b * MAXM * 4)[tid];
        s_gt[tid] = g;
        // Faithful to reference: rows from x, cols from y.
        int row = min(max((int)floorf(g.x * 7.0f), 0), S_GRID - 1);
        int col = min(max((int)floorf(g.y * 7.0f), 0), S_GRID - 1);
        s_cell[tid] = row * S_GRID + col;
        s_cls[tid] = gt_class[(size_t)b * MAXM + tid];
    }
    __syncthreads();

    if (tid < MAXM) {
        int c = s_cell[tid];
        int k = 1;
        for (int m = 0; m < tid; m++)
            if (s_cell[m] == c) k = 0;      // first-occurrence-per-cell dedup
        s_keep[tid] = k;
    }
    if (tid == 0) {
        unsigned long long msk = 0ull;
        for (int m = 0; m < MAXM; m++) msk |= 1ull << s_cell[m];
        s_obj = msk;
    }
    __syncthreads();

    float acc = 0.0f;

    // No-object confidence term: 49 cells x 2 confidence channels (4, 9).
    if (tid < 2 * CELLS) {
        int cell = tid >> 1;
        if (!((s_obj >> cell) & 1ull)) {
            float v = tile[cell * CH + ((tid & 1) ? 9 : 4)];
            acc += 0.5f * v * v;            // LAMBDA_NOOBJ
        }
    }

    // Per-box terms.
    if (tid < MAXM && s_keep[tid]) {
        float4 g = s_gt[tid];
        int cell = s_cell[tid];
        int row = cell / S_GRID;
        int col = cell - row * S_GRID;
        // Faithful to reference: tgt.x uses col (from y), tgt.y uses row (from x).
        float tx = g.x * 7.0f - (float)col;
        float ty = g.y * 7.0f - (float)row;
        float tw = sqrtf(g.z);
        float th = sqrtf(g.w);
        const float* cp = &tile[cell * CH];

        float i1 = iou_fn(cp[0], cp[1], cp[2], cp[3], tx, ty, tw, th);
        float i2 = iou_fn(cp[5], cp[6], cp[7], cp[8], tx, ty, tw, th);
        bool use2 = (i2 >= i1);
        int o = use2 ? 5 : 0;

        float d0 = cp[o + 0] - tx;
        float d1 = cp[o + 1] - ty;
        float d2 = cp[o + 2] - tw;
        float d3 = cp[o + 3] - th;
        acc += 5.0f * (d0 * d0 + d1 * d1 + d2 * d2 + d3 * d3);   // LAMBDA_COORD

        float sc = cp[o + 4];
        float si = use2 ? i2 : i1;
        float dc = sc - si;
        acc += dc * dc;

        int cl = s_cls[tid];
        #pragma unroll
        for (int c = 0; c < NUMC; c++) {
            float d = cp[10 + c] - ((c == cl) ? 1.0f : 0.0f);
            acc += d * d;
        }
    }

    // Block reduce (128 threads = 4 warps).
    #pragma unroll
    for (int off = 16; off > 0; off >>= 1)
        acc += __shfl_down_sync(0xffffffffu, acc, off);
    if ((tid & 31) == 0) s_red[tid >> 5] = acc;
    __syncthreads();
    if (tid == 0)
        g_partial[b] = s_red[0] + s_red[1] + s_red[2] + s_red[3];
}

__global__ __launch_bounds__(256) void reduce_kernel(float* __restrict__ out, int Bn) {
    __shared__ float sh[256];
    int tid = threadIdx.x;
    float s = 0.0f;
    for (int i = tid; i < Bn; i += 256) s += g_partial[i];
    sh[tid] = s;
    __syncthreads();
    #pragma unroll
    for (int st = 128; st > 0; st >>= 1) {
        if (tid < st) sh[tid] += sh[tid + st];
        __syncthreads();
    }
    if (tid == 0) out[0] = sh[0] / (float)Bn;
}

extern "C" void kernel_launch(void* const* d_in, const int* in_sizes, int n_in,
                              void* d_out, int out_size) {
    const float* pred    = (const float*)d_in[0];
    const float* gt_xywh = (const float*)d_in[1];
    const int*   gt_cls  = (const int*)d_in[2];
    float* out = (float*)d_out;

    int B = in_sizes[0] / TILE_ELEMS;   // 16384

    yolo_loss_kernel<<<B, 128>>>(pred, gt_xywh, gt_cls);
    reduce_kernel<<<1, 256>>>(out, B);
}

// round 3
// speedup vs baseline: 1.7175x; 1.7175x over previous
#include <cuda_runtime.h>
#include <cuda_bf16.h>

#define S_GRID 7
#define CH 30
#define TILE 1470          // 7*7*30
#define MAXM 16
#define NUMC 20
#define IPB 8              // images per block
#define MAXPART 4096       // >= B/IPB

__device__ float g_partial[MAXPART];
__device__ unsigned int g_count = 0;   // reset by last block each launch

__device__ __forceinline__ float iou_fn(float a0, float a1, float a2, float a3,
                                        float b0, float b1, float b2, float b3) {
    float ax1 = a0 - a2 * 0.5f, ay1 = a1 - a3 * 0.5f;
    float ax2 = a0 + a2 * 0.5f, ay2 = a1 + a3 * 0.5f;
    float bx1 = b0 - b2 * 0.5f, by1 = b1 - b3 * 0.5f;
    float bx2 = b0 + b2 * 0.5f, by2 = b1 + b3 * 0.5f;
    float iw = fmaxf(fminf(ax2, bx2) - fmaxf(ax1, bx1), 0.0f);
    float ih = fmaxf(fminf(ay2, by2) - fmaxf(ay1, by1), 0.0f);
    float inter = iw * ih;
    float uni = a2 * a3 + b2 * b3 - inter;
    return inter / (uni + 1e-6f);
}

__device__ __forceinline__ float block_reduce_128(float v, float* s_red, int t) {
    #pragma unroll
    for (int off = 16; off > 0; off >>= 1)
        v += __shfl_down_sync(0xffffffffu, v, off);
    if ((t & 31) == 0) s_red[t >> 5] = v;
    __syncthreads();
    return s_red[0] + s_red[1] + s_red[2] + s_red[3];
}

__global__ __launch_bounds__(128) void yolo_loss_fused(
    const float* __restrict__ pred,
    const float* __restrict__ gt_xywh,
    const int*   __restrict__ gt_class,
    float* __restrict__ out,
    int nblk, int Btot) {

    const int t = threadIdx.x;
    const long long b0 = (long long)blockIdx.x * IPB;

    __shared__ int s_cell[IPB][MAXM];
    __shared__ unsigned long long s_obj[IPB];
    __shared__ float s_red[4];
    __shared__ int s_last;

    // ---- gt metadata: one box per thread, fully coalesced float4 / int ----
    float4 g = reinterpret_cast<const float4*>(gt_xywh)[(long long)blockIdx.x * 128 + t];
    int cls  = gt_class[(long long)blockIdx.x * 128 + t];
    const int img = t >> 4;        // 0..7
    const int m   = t & 15;        // 0..15
    // Faithful to reference: row from x, col from y.
    int row = min(max((int)floorf(g.x * 7.0f), 0), S_GRID - 1);
    int col = min(max((int)floorf(g.y * 7.0f), 0), S_GRID - 1);
    int cell = row * S_GRID + col;
    s_cell[img][m] = cell;
    __syncthreads();

    if (t < IPB) {
        unsigned long long msk = 0ull;
        #pragma unroll
        for (int i = 0; i < MAXM; i++) msk |= 1ull << s_cell[t][i];
        s_obj[t] = msk;
    }
    // first-occurrence-per-cell dedup
    int keep = 1;
    for (int i = 0; i < m; i++)
        if (s_cell[img][i] == cell) keep = 0;
    __syncthreads();

    float acc = 0.0f;

    // ---- no-object confidence: masked scattered 4B loads, 8-deep MLP ----
    if (t < 2 * S_GRID * S_GRID) {
        const int c  = t >> 1;
        const int ch = (t & 1) ? 9 : 4;
        #pragma unroll
        for (int i = 0; i < IPB; i++) {
            if (!((s_obj[i] >> c) & 1ull)) {
                float v = __ldg(&pred[(b0 + i) * TILE + c * CH + ch]);
                acc += 0.5f * v * v;             // LAMBDA_NOOBJ
            }
        }
    }

    // ---- per-box terms: thread t owns (img, m) ----
    if (keep) {
        float tx = g.x * 7.0f - (float)col;      // faithful x/y swap
        float ty = g.y * 7.0f - (float)row;
        float tw = sqrtf(g.z);
        float th = sqrtf(g.w);
        const float2* rp = reinterpret_cast<const float2*>(
            &pred[(b0 + img) * TILE + cell * CH]);   // 8B-aligned row

        float2 v0 = __ldg(&rp[0]);   // ch0,1
        float2 v1 = __ldg(&rp[1]);   // ch2,3
        float2 v2 = __ldg(&rp[2]);   // ch4,5
        float2 v3 = __ldg(&rp[3]);   // ch6,7
        float2 v4 = __ldg(&rp[4]);   // ch8,9

        float i1 = iou_fn(v0.x, v0.y, v1.x, v1.y, tx, ty, tw, th);
        float i2 = iou_fn(v2.y, v3.x, v3.y, v4.x, tx, ty, tw, th);
        bool use2 = (i2 >= i1);
        float bx = use2 ? v2.y : v0.x;
        float by = use2 ? v3.x : v0.y;
        float bw = use2 ? v3.y : v1.x;
        float bh = use2 ? v4.x : v1.y;
        float sc = use2 ? v4.y : v2.x;
        float si = use2 ? i2   : i1;

        float d0 = bx - tx, d1 = by - ty, d2 = bw - tw, d3 = bh - th;
        acc += 5.0f * (d0 * d0 + d1 * d1 + d2 * d2 + d3 * d3);  // LAMBDA_COORD
        float dc = sc - si;
        acc += dc * dc;

        // classes: channels 10..29, streamed as float2
        #pragma unroll
        for (int i = 0; i < 10; i++) {
            float2 v = __ldg(&rp[5 + i]);
            float e0 = v.x - ((2 * i     == cls) ? 1.0f : 0.0f);
            float e1 = v.y - ((2 * i + 1 == cls) ? 1.0f : 0.0f);
            acc += e0 * e0 + e1 * e1;
        }
    }

    // ---- block partial ----
    float tot = block_reduce_128(acc, s_red, t);
    if (t == 0) g_partial[blockIdx.x] = tot;

    // ---- fused final reduction: last block finishes ----
    __threadfence();
    if (t == 0) {
        unsigned int ticket = atomicAdd(&g_count, 1u);
        s_last = (ticket == (unsigned int)(nblk - 1));
    }
    __syncthreads();
    if (s_last) {
        __threadfence();
        float s = 0.0f;
        for (int i = t; i < nblk; i += 128)
            s += __ldcg(&g_partial[i]);
        __syncthreads();          // s_red reuse
        float fin = block_reduce_128(s, s_red, t);
        if (t == 0) {
            out[0] = fin / (float)Btot;
            g_count = 0;          // ready for next (replay) launch
        }
    }
}

extern "C" void kernel_launch(void* const* d_in, const int* in_sizes, int n_in,
                              void* d_out, int out_size) {
    const float* pred    = (const float*)d_in[0];
    const float* gt_xywh = (const float*)d_in[1];
    const int*   gt_cls  = (const int*)d_in[2];
    float* out = (float*)d_out;

    int B = in_sizes[0] / TILE;     // 16384
    int nblk = B / IPB;             // 2048

    yolo_loss_fused<<<nblk, 128>>>(pred, gt_xywh, gt_cls, out, nblk, B);
}